// round 1
// baseline (speedup 1.0000x reference)
#include <cuda_runtime.h>
#include <math.h>

// Problem constants
#define Bc   16
#define Tc   16
#define Hc   161
#define Wc   181
#define Cc   3
#define Fc   21
#define F4c  84
#define CINc 24                 // Cc + Fc combined input channels
#define HWc  (Hc*Wc)            // 29141

// Tiling
#define TW   32
#define TH   8
#define HLW  (TW+2)             // 34
#define HLH  (TH+2)             // 10
#define TILE_ELEMS (CINc*HLH*HLW)   // 8160
#define WSZ  (9*CINc*F4c)           // 18144
#define SMEM_FLOATS (TILE_ELEMS + WSZ + F4c)
#define SMEM_BYTES  (SMEM_FLOATS*4) // 105,888 B

// Persistent device state (allowed: __device__ globals, no runtime alloc)
__device__ float g_Wpack[WSZ];               // [tap][cin][cout]
__device__ float g_h0[Bc*Fc*HWc];            // planar [b][f][h*w]
__device__ float g_h1[Bc*Fc*HWc];
__device__ float g_c [Bc*Fc*HWc];

__device__ __forceinline__ float hsig(float v) {
    return fminf(fmaxf(0.2f*v + 0.5f, 0.0f), 1.0f);
}

// ---------------------------------------------------------------------------
// Pack Wx (3,3,3,84) and Wh (3,3,21,84) into unified [9][24][84]
// ---------------------------------------------------------------------------
__global__ void pack_kernel(const float* __restrict__ k, const float* __restrict__ rk) {
    int i = blockIdx.x*blockDim.x + threadIdx.x;
    if (i >= WSZ) return;
    int kk  = i / (CINc*F4c);
    int r   = i - kk*(CINc*F4c);
    int cin = r / F4c;
    int co  = r - cin*F4c;
    float v;
    if (cin < Cc) v = k [(kk*Cc + cin)*F4c + co];
    else          v = rk[(kk*Fc + (cin-Cc))*F4c + co];
    g_Wpack[i] = v;
}

// ---------------------------------------------------------------------------
// Zero h0 and c state
// ---------------------------------------------------------------------------
__global__ void zero_kernel() {
    const int n = Bc*Fc*HWc;
    for (int i = blockIdx.x*blockDim.x + threadIdx.x; i < n; i += gridDim.x*blockDim.x) {
        g_h0[i] = 0.0f;
        g_c [i] = 0.0f;
    }
}

// ---------------------------------------------------------------------------
// One ConvLSTM timestep: z = conv(x_t ++ h, Wpack) + bias; gate update.
// dir=0: h_in=g_h0, h_out=g_h1;  dir=1: h_in=g_h1, h_out=g_h0.
// ---------------------------------------------------------------------------
__global__ __launch_bounds__(256, 2)
void step_kernel(const float* __restrict__ x, const float* __restrict__ bias,
                 int t, int dir) {
    extern __shared__ float sm[];
    float* s_tile = sm;                     // [CIN][HLH][HLW]
    float* s_W    = sm + TILE_ELEMS;        // [9*CIN][84], 16B aligned
    float* s_bias = s_W + WSZ;

    const float* h_in  = dir ? g_h1 : g_h0;
    float*       h_out = dir ? g_h0 : g_h1;

    const int tid = threadIdx.x;
    const int bx = blockIdx.x, by = blockIdx.y, b = blockIdx.z;
    const int x0 = bx*TW, y0 = by*TH;

    // Stage weights (vectorized) + bias
    {
        const float4* gw4 = reinterpret_cast<const float4*>(g_Wpack);
        float4*       sw4 = reinterpret_cast<float4*>(s_W);
        #pragma unroll 4
        for (int i = tid; i < WSZ/4; i += 256) sw4[i] = gw4[i];
        if (tid < F4c) s_bias[tid] = bias[tid];
    }

    // Stage halo tile: channels 0..2 = x_t, channels 3..23 = h_in; zero-pad OOB
    for (int i = tid; i < TILE_ELEMS; i += 256) {
        int cin = i / (HLH*HLW);
        int r   = i - cin*(HLH*HLW);
        int row = r / HLW;
        int col = r - row*HLW;
        int gy = y0 + row - 1;
        int gx = x0 + col - 1;
        float v = 0.0f;
        if ((unsigned)gy < (unsigned)Hc && (unsigned)gx < (unsigned)Wc) {
            if (cin < Cc)
                v = x[(((size_t)(b*Tc + t)*Hc + gy)*Wc + gx)*Cc + cin];
            else
                v = h_in[((size_t)(b*Fc + (cin - Cc)))*HWc + (size_t)gy*Wc + gx];
        }
        s_tile[i] = v;
    }
    __syncthreads();

    const int tx = tid & 31;
    const int ty = tid >> 5;

    float acc[F4c];
    #pragma unroll
    for (int co = 0; co < F4c; co++) acc[co] = s_bias[co];

    // Main accumulation: FFMA-bound (84 FFMA vs 22 LDS per (cin,tap) iter)
    #pragma unroll 1
    for (int cin = 0; cin < CINc; cin++) {
        const float* tp = s_tile + cin*(HLH*HLW) + ty*HLW + tx;
        #pragma unroll
        for (int kk = 0; kk < 9; kk++) {
            const int dy = kk / 3, dx = kk - 3*(kk/3);
            const float d = tp[dy*HLW + dx];
            const float4* w = reinterpret_cast<const float4*>(s_W + (kk*CINc + cin)*F4c);
            #pragma unroll
            for (int j = 0; j < F4c/4; j++) {
                float4 wv = w[j];
                acc[4*j+0] = fmaf(d, wv.x, acc[4*j+0]);
                acc[4*j+1] = fmaf(d, wv.y, acc[4*j+1]);
                acc[4*j+2] = fmaf(d, wv.z, acc[4*j+2]);
                acc[4*j+3] = fmaf(d, wv.w, acc[4*j+3]);
            }
        }
    }

    // Gate epilogue
    const int ox = x0 + tx, oy = y0 + ty;
    if (ox < Wc && oy < Hc) {
        const size_t p = (size_t)oy*Wc + ox;
        #pragma unroll
        for (int co = 0; co < Fc; co++) {
            float ig = hsig(acc[co]);
            float fg = hsig(acc[co + Fc]);
            float gg = tanhf(acc[co + 2*Fc]);
            float og = hsig(acc[co + 3*Fc]);
            size_t idx = ((size_t)(b*Fc + co))*HWc + p;
            float cn = fg * g_c[idx] + ig * gg;
            g_c[idx] = cn;
            h_out[idx] = og * tanhf(cn);
        }
    }
}

// ---------------------------------------------------------------------------
// out[b,h,w,f] = h_final(planar)[b,f,h,w] * mask[h,w]
// ---------------------------------------------------------------------------
__global__ void mask_out_kernel(const float* __restrict__ mask, float* __restrict__ out) {
    const int n = Bc*HWc*Fc;
    int i = blockIdx.x*blockDim.x + threadIdx.x;
    if (i >= n) return;
    int co   = i % Fc;
    int rest = i / Fc;
    int p    = rest % HWc;
    int b    = rest / HWc;
    // final h lives in g_h0 (16 steps -> even parity)
    out[i] = g_h0[((size_t)(b*Fc + co))*HWc + p] * mask[p];
}

// ---------------------------------------------------------------------------
extern "C" void kernel_launch(void* const* d_in, const int* in_sizes, int n_in,
                              void* d_out, int out_size) {
    const float* x     = (const float*)d_in[0];
    const float* kern  = (const float*)d_in[1];
    const float* rkern = (const float*)d_in[2];
    const float* bias  = (const float*)d_in[3];
    const float* mask  = (const float*)d_in[4];
    float* out = (float*)d_out;
    (void)in_sizes; (void)n_in; (void)out_size;

    cudaFuncSetAttribute(step_kernel, cudaFuncAttributeMaxDynamicSharedMemorySize,
                         SMEM_BYTES);

    pack_kernel<<<(WSZ + 255)/256, 256>>>(kern, rkern);
    zero_kernel<<<4096, 256>>>();

    dim3 grid((Wc + TW - 1)/TW, (Hc + TH - 1)/TH, Bc);  // (6, 21, 16)
    for (int t = 0; t < Tc; t++) {
        step_kernel<<<grid, 256, SMEM_BYTES>>>(x, bias, t, t & 1);
    }

    const int n = Bc*HWc*Fc;
    mask_out_kernel<<<(n + 255)/256, 256>>>(mask, out);
}

// round 2
// speedup vs baseline: 1.0780x; 1.0780x over previous
#include <cuda_runtime.h>
#include <math.h>

// Problem constants
#define Bc   16
#define Tc   16
#define Hc   161
#define Wc   181
#define Cc   3
#define Fc   21
#define F4c  84
#define CINc 24                 // Cc + Fc combined input channels
#define HWc  (Hc*Wc)            // 29141

// Tiling
#define TW   32
#define TH   8
#define HLW  (TW+2)             // 34
#define HLH  (TH+2)             // 10
#define TILE_ELEMS (CINc*HLH*HLW)   // 8160
#define WSZ  (9*CINc*F4c)           // 18144
#define SMEM_FLOATS (TILE_ELEMS + WSZ + F4c)
#define SMEM_BYTES  (SMEM_FLOATS*4) // 105,888 B

#define NPAIR (F4c/2)           // 42 packed f32x2 accumulators

// Persistent device state
__device__ float g_Wpack[WSZ];               // [tap][cin][cout]
__device__ float g_h0[Bc*Fc*HWc];            // planar [b][f][h*w]
__device__ float g_h1[Bc*Fc*HWc];
__device__ float g_c [Bc*Fc*HWc];

__device__ __forceinline__ float hsig(float v) {
    return fminf(fmaxf(0.2f*v + 0.5f, 0.0f), 1.0f);
}

// ---------------------------------------------------------------------------
__global__ void pack_kernel(const float* __restrict__ k, const float* __restrict__ rk) {
    int i = blockIdx.x*blockDim.x + threadIdx.x;
    if (i >= WSZ) return;
    int kk  = i / (CINc*F4c);
    int r   = i - kk*(CINc*F4c);
    int cin = r / F4c;
    int co  = r - cin*F4c;
    float v;
    if (cin < Cc) v = k [(kk*Cc + cin)*F4c + co];
    else          v = rk[(kk*Fc + (cin-Cc))*F4c + co];
    g_Wpack[i] = v;
}

__global__ void zero_kernel() {
    const int n = Bc*Fc*HWc;
    for (int i = blockIdx.x*blockDim.x + threadIdx.x; i < n; i += gridDim.x*blockDim.x) {
        g_h0[i] = 0.0f;
        g_c [i] = 0.0f;
    }
}

// ---------------------------------------------------------------------------
// One ConvLSTM timestep using packed f32x2 FFMA2 (2 floats per FMA issue).
// ---------------------------------------------------------------------------
__global__ __launch_bounds__(256, 2)
void step_kernel(const float* __restrict__ x, const float* __restrict__ bias,
                 int t, int dir) {
    extern __shared__ float sm[];
    float* s_tile = sm;                     // [CIN][HLH][HLW]
    float* s_W    = sm + TILE_ELEMS;        // [9*CIN][84], rows 336B (16B-aligned)
    float* s_bias = s_W + WSZ;

    const float* h_in  = dir ? g_h1 : g_h0;
    float*       h_out = dir ? g_h0 : g_h1;

    const int tid = threadIdx.x;
    const int bx = blockIdx.x, by = blockIdx.y, b = blockIdx.z;
    const int x0 = bx*TW, y0 = by*TH;

    // Stage weights (vectorized) + bias
    {
        const float4* gw4 = reinterpret_cast<const float4*>(g_Wpack);
        float4*       sw4 = reinterpret_cast<float4*>(s_W);
        #pragma unroll 4
        for (int i = tid; i < WSZ/4; i += 256) sw4[i] = gw4[i];
        if (tid < F4c) s_bias[tid] = bias[tid];
    }

    // Stage halo tile: ch 0..2 = x_t, ch 3..23 = h_in; zero-pad OOB
    for (int i = tid; i < TILE_ELEMS; i += 256) {
        int cin = i / (HLH*HLW);
        int r   = i - cin*(HLH*HLW);
        int row = r / HLW;
        int col = r - row*HLW;
        int gy = y0 + row - 1;
        int gx = x0 + col - 1;
        float v = 0.0f;
        if ((unsigned)gy < (unsigned)Hc && (unsigned)gx < (unsigned)Wc) {
            if (cin < Cc)
                v = x[(((size_t)(b*Tc + t)*Hc + gy)*Wc + gx)*Cc + cin];
            else
                v = h_in[((size_t)(b*Fc + (cin - Cc)))*HWc + (size_t)gy*Wc + gx];
        }
        s_tile[i] = v;
    }
    __syncthreads();

    const int tx = tid & 31;
    const int ty = tid >> 5;

    // 42 packed f32x2 accumulators, init from bias (s_bias is 8B-aligned)
    unsigned long long acc[NPAIR];
    {
        const unsigned long long* b2 = reinterpret_cast<const unsigned long long*>(s_bias);
        #pragma unroll
        for (int j = 0; j < NPAIR; j++) acc[j] = b2[j];
    }

    // Main accumulation: 42 FFMA2 + 22 LDS per (cin,tap) iter — fma-pipe bound
    #pragma unroll 1
    for (int cin = 0; cin < CINc; cin++) {
        const float* tp = s_tile + cin*(HLH*HLW) + ty*HLW + tx;
        #pragma unroll
        for (int kk = 0; kk < 9; kk++) {
            const int dy = kk / 3, dx = kk - 3*(kk/3);
            const float d = tp[dy*HLW + dx];
            unsigned long long d2;
            asm("mov.b64 %0, {%1, %1};" : "=l"(d2) : "f"(d));
            const ulonglong2* w = reinterpret_cast<const ulonglong2*>(
                s_W + (kk*CINc + cin)*F4c);            // 336B row = 21 x 16B
            #pragma unroll
            for (int j = 0; j < NPAIR/2; j++) {        // 21 LDS.128 -> 42 FFMA2
                ulonglong2 wv = w[j];
                asm("fma.rn.f32x2 %0, %1, %2, %0;" : "+l"(acc[2*j  ]) : "l"(d2), "l"(wv.x));
                asm("fma.rn.f32x2 %0, %1, %2, %0;" : "+l"(acc[2*j+1]) : "l"(d2), "l"(wv.y));
            }
        }
    }

    // Gate epilogue (unpack pairs to scalars first)
    const int ox = x0 + tx, oy = y0 + ty;
    if (ox < Wc && oy < Hc) {
        float a[F4c];
        #pragma unroll
        for (int j = 0; j < NPAIR; j++) {
            asm("mov.b64 {%0, %1}, %2;" : "=f"(a[2*j]), "=f"(a[2*j+1]) : "l"(acc[j]));
        }
        const size_t p = (size_t)oy*Wc + ox;
        #pragma unroll
        for (int co = 0; co < Fc; co++) {
            float ig = hsig(a[co]);
            float fg = hsig(a[co + Fc]);
            float gg = tanhf(a[co + 2*Fc]);
            float og = hsig(a[co + 3*Fc]);
            size_t idx = ((size_t)(b*Fc + co))*HWc + p;
            float cn = fg * g_c[idx] + ig * gg;
            g_c[idx] = cn;
            h_out[idx] = og * tanhf(cn);
        }
    }
}

// ---------------------------------------------------------------------------
__global__ void mask_out_kernel(const float* __restrict__ mask, float* __restrict__ out) {
    const int n = Bc*HWc*Fc;
    int i = blockIdx.x*blockDim.x + threadIdx.x;
    if (i >= n) return;
    int co   = i % Fc;
    int rest = i / Fc;
    int p    = rest % HWc;
    int b    = rest / HWc;
    out[i] = g_h0[((size_t)(b*Fc + co))*HWc + p] * mask[p];
}

// ---------------------------------------------------------------------------
extern "C" void kernel_launch(void* const* d_in, const int* in_sizes, int n_in,
                              void* d_out, int out_size) {
    const float* x     = (const float*)d_in[0];
    const float* kern  = (const float*)d_in[1];
    const float* rkern = (const float*)d_in[2];
    const float* bias  = (const float*)d_in[3];
    const float* mask  = (const float*)d_in[4];
    float* out = (float*)d_out;
    (void)in_sizes; (void)n_in; (void)out_size;

    cudaFuncSetAttribute(step_kernel, cudaFuncAttributeMaxDynamicSharedMemorySize,
                         SMEM_BYTES);

    pack_kernel<<<(WSZ + 255)/256, 256>>>(kern, rkern);
    zero_kernel<<<4096, 256>>>();

    dim3 grid((Wc + TW - 1)/TW, (Hc + TH - 1)/TH, Bc);  // (6, 21, 16)
    for (int t = 0; t < Tc; t++) {
        step_kernel<<<grid, 256, SMEM_BYTES>>>(x, bias, t, t & 1);
    }

    const int n = Bc*HWc*Fc;
    mask_out_kernel<<<(n + 255)/256, 256>>>(mask, out);
}

// round 3
// speedup vs baseline: 1.2008x; 1.1140x over previous
#include <cuda_runtime.h>
#include <math.h>

// Problem constants
#define Bc   16
#define Tc   16
#define Hc   161
#define Wc   181
#define Cc   3
#define Fc   21
#define F4c  84
#define CINc 24
#define HWc  (Hc*Wc)            // 29141

// Tiling
#define TW   32
#define TH   8
#define HLW  (TW+2)             // 34
#define HLH  (TH+2)             // 10
#define TILE_ELEMS (CINc*HLH*HLW)   // 8160
// Weights packed gate-major: [tap][cin][22 co][4 gates], co 21 = zero pad
#define WROW 88
#define WSZ  (9*CINc*WROW)          // 19008
#define SMEM_FLOATS (TILE_ELEMS + WSZ + WROW)
#define SMEM_BYTES  (SMEM_FLOATS*4) // 109,024 B

typedef unsigned long long ull;

// Persistent device state
__device__ float g_Wpack[WSZ];
__device__ float g_h0[Bc*Fc*HWc];
__device__ float g_h1[Bc*Fc*HWc];
__device__ float g_c [Bc*Fc*HWc];

__device__ __forceinline__ float hsig(float v) {
    return fminf(fmaxf(0.2f*v + 0.5f, 0.0f), 1.0f);
}

// ---------------------------------------------------------------------------
// Pack Wx (3,3,3,84) + Wh (3,3,21,84) into [9][24][22][4] gate-major, padded.
// source col for (co, g) = g*21 + co
// ---------------------------------------------------------------------------
__global__ void pack_kernel(const float* __restrict__ k, const float* __restrict__ rk) {
    int i = blockIdx.x*blockDim.x + threadIdx.x;
    if (i >= WSZ) return;
    int kk  = i / (CINc*WROW);
    int r   = i - kk*(CINc*WROW);
    int cin = r / WROW;
    int q   = r - cin*WROW;
    int co  = q >> 2;
    int g   = q & 3;
    float v = 0.0f;
    if (co < Fc) {
        int col = g*Fc + co;
        if (cin < Cc) v = k [(kk*Cc + cin)*F4c + col];
        else          v = rk[(kk*Fc + (cin-Cc))*F4c + col];
    }
    g_Wpack[i] = v;
}

__global__ void zero_kernel() {
    const int n = Bc*Fc*HWc;
    for (int i = blockIdx.x*blockDim.x + threadIdx.x; i < n; i += gridDim.x*blockDim.x) {
        g_h0[i] = 0.0f;
        g_c [i] = 0.0f;
    }
}

// ---------------------------------------------------------------------------
// One ConvLSTM timestep. 256 thr: 2 cout-groups x 128 thr; each thread does
// 2 vertically-adjacent pixels x 11 couts x 4 gates, FFMA2 packed over gates.
// ---------------------------------------------------------------------------
__global__ __launch_bounds__(256, 2)
void step_kernel(const float* __restrict__ x, const float* __restrict__ bias,
                 int t, int dir) {
    extern __shared__ float sm[];
    float* s_tile = sm;                     // [CIN][HLH][HLW]
    float* s_W    = sm + TILE_ELEMS;        // [9*CIN][88]
    float* s_bias = s_W + WSZ;              // [88] gate-major packed

    const float* h_in  = dir ? g_h1 : g_h0;
    float*       h_out = dir ? g_h0 : g_h1;

    const int tid = threadIdx.x;
    const int bx = blockIdx.x, by = blockIdx.y, b = blockIdx.z;
    const int x0 = bx*TW, y0 = by*TH;

    // Stage weights (vectorized) + packed bias
    {
        const float4* gw4 = reinterpret_cast<const float4*>(g_Wpack);
        float4*       sw4 = reinterpret_cast<float4*>(s_W);
        #pragma unroll 4
        for (int i = tid; i < WSZ/4; i += 256) sw4[i] = gw4[i];
        if (tid < F4c) s_bias[tid] = bias[(tid & 3)*Fc + (tid >> 2)];
        else if (tid < WROW) s_bias[tid] = 0.0f;
    }

    // Stage halo tile: ch 0..2 = x_t, ch 3..23 = h_in; zero-pad OOB
    for (int i = tid; i < TILE_ELEMS; i += 256) {
        int cin = i / (HLH*HLW);
        int r   = i - cin*(HLH*HLW);
        int row = r / HLW;
        int col = r - row*HLW;
        int gy = y0 + row - 1;
        int gx = x0 + col - 1;
        float v = 0.0f;
        if ((unsigned)gy < (unsigned)Hc && (unsigned)gx < (unsigned)Wc) {
            if (cin < Cc)
                v = x[(((size_t)(b*Tc + t)*Hc + gy)*Wc + gx)*Cc + cin];
            else
                v = h_in[((size_t)(b*Fc + (cin - Cc)))*HWc + (size_t)gy*Wc + gx];
        }
        s_tile[i] = v;
    }
    __syncthreads();

    const int group = tid >> 7;          // 0: co 0..10, 1: co 11..21(pad)
    const int rr    = tid & 127;
    const int tx    = rr & 31;
    const int row2  = (rr >> 5) * 2;     // 0,2,4,6
    const int cobase = group * 11;

    // Accumulators: 2 pixels x 11 co x 2 pairs ({i,f},{g,o}) = 44 ull
    ull acc0[22], acc1[22];
    {
        const ull* b2 = reinterpret_cast<const ull*>(s_bias + cobase*4);
        #pragma unroll
        for (int j = 0; j < 22; j++) { acc0[j] = b2[j]; acc1[j] = b2[j]; }
    }

    // Mainloop: per (cin,tap): 11 LDS.128 weights + 2 data LDS, 44 FFMA2
    #pragma unroll 1
    for (int cin = 0; cin < CINc; cin++) {
        const float* tp = s_tile + cin*(HLH*HLW) + row2*HLW + tx;
        #pragma unroll
        for (int kk = 0; kk < 9; kk++) {
            const int dy = kk/3, dx = kk - 3*(kk/3);
            const float da = tp[dy*HLW + dx];
            const float db = tp[(dy+1)*HLW + dx];
            ull d2a, d2b;
            asm("mov.b64 %0, {%1, %1};" : "=l"(d2a) : "f"(da));
            asm("mov.b64 %0, {%1, %1};" : "=l"(d2b) : "f"(db));
            const ulonglong2* w = reinterpret_cast<const ulonglong2*>(
                s_W + (kk*CINc + cin)*WROW + cobase*4);
            #pragma unroll
            for (int j = 0; j < 11; j++) {
                ulonglong2 wv = w[j];
                asm("fma.rn.f32x2 %0, %1, %2, %0;" : "+l"(acc0[2*j  ]) : "l"(d2a), "l"(wv.x));
                asm("fma.rn.f32x2 %0, %1, %2, %0;" : "+l"(acc0[2*j+1]) : "l"(d2a), "l"(wv.y));
                asm("fma.rn.f32x2 %0, %1, %2, %0;" : "+l"(acc1[2*j  ]) : "l"(d2b), "l"(wv.x));
                asm("fma.rn.f32x2 %0, %1, %2, %0;" : "+l"(acc1[2*j+1]) : "l"(d2b), "l"(wv.y));
            }
        }
    }

    // Gate epilogue: each thread owns full (i,f,g,o) per co, both pixels
    const int ox = x0 + tx;
    #pragma unroll
    for (int px = 0; px < 2; px++) {
        const int oy = y0 + row2 + px;
        if (ox < Wc && oy < Hc) {
            const ull* ac = px ? acc1 : acc0;
            const size_t p = (size_t)oy*Wc + ox;
            #pragma unroll
            for (int j = 0; j < 11; j++) {
                const int co = cobase + j;
                if (co >= Fc) break;
                float zi, zf, zg, zo;
                asm("mov.b64 {%0, %1}, %2;" : "=f"(zi), "=f"(zf) : "l"(ac[2*j  ]));
                asm("mov.b64 {%0, %1}, %2;" : "=f"(zg), "=f"(zo) : "l"(ac[2*j+1]));
                float ig = hsig(zi);
                float fg = hsig(zf);
                float gg = tanhf(zg);
                float og = hsig(zo);
                size_t idx = ((size_t)(b*Fc + co))*HWc + p;
                float cn = fg * g_c[idx] + ig * gg;
                g_c[idx] = cn;
                h_out[idx] = og * tanhf(cn);
            }
        }
    }
}

// ---------------------------------------------------------------------------
__global__ void mask_out_kernel(const float* __restrict__ mask, float* __restrict__ out) {
    const int n = Bc*HWc*Fc;
    int i = blockIdx.x*blockDim.x + threadIdx.x;
    if (i >= n) return;
    int co   = i % Fc;
    int rest = i / Fc;
    int p    = rest % HWc;
    int b    = rest / HWc;
    out[i] = g_h0[((size_t)(b*Fc + co))*HWc + p] * mask[p];
}

// ---------------------------------------------------------------------------
extern "C" void kernel_launch(void* const* d_in, const int* in_sizes, int n_in,
                              void* d_out, int out_size) {
    const float* x     = (const float*)d_in[0];
    const float* kern  = (const float*)d_in[1];
    const float* rkern = (const float*)d_in[2];
    const float* bias  = (const float*)d_in[3];
    const float* mask  = (const float*)d_in[4];
    float* out = (float*)d_out;
    (void)in_sizes; (void)n_in; (void)out_size;

    cudaFuncSetAttribute(step_kernel, cudaFuncAttributeMaxDynamicSharedMemorySize,
                         SMEM_BYTES);

    pack_kernel<<<(WSZ + 255)/256, 256>>>(kern, rkern);
    zero_kernel<<<4096, 256>>>();

    dim3 grid((Wc + TW - 1)/TW, (Hc + TH - 1)/TH, Bc);  // (6, 21, 16)
    for (int t = 0; t < Tc; t++) {
        step_kernel<<<grid, 256, SMEM_BYTES>>>(x, bias, t, t & 1);
    }

    const int n = Bc*HWc*Fc;
    mask_out_kernel<<<(n + 255)/256, 256>>>(mask, out);
}